// round 9
// baseline (speedup 1.0000x reference)
#include <cuda_runtime.h>
#include <math.h>

#define BATCH 2
#define SEQ   2048
#define DIM   1024
#define HEADS 16
#define HD    64
#define MTOT  (BATCH*SEQ)     // 4096
#define EQKV  (3*DIM)         // 3072
#define PAD   68              // 64 + 4 (keeps float4 alignment: 68*4=272 bytes/row)

// Scratch (allocation-free rule: __device__ globals)
__device__ float g_Q[BATCH*HEADS*SEQ*HD];   // [B,H,N,hd]
__device__ float g_K[BATCH*HEADS*SEQ*HD];
__device__ float g_V[BATCH*HEADS*SEQ*HD];
__device__ float g_AO[(size_t)MTOT*DIM];    // attention output, [B,N,D]

// ---------------------------------------------------------------------------
// QKV projection: C[m,e] = sum_k X[m,k] * W_qkv[e,k] + b_qkv[e]
// scattered directly into g_Q/g_K/g_V with [B,H,N,hd] layout.
// 64x64 tile, BK=16, 256 threads, 4x4 register block per thread.
// ---------------------------------------------------------------------------
__global__ void __launch_bounds__(256) qkv_gemm(const float* __restrict__ A,
                                                const float* __restrict__ W,
                                                const float* __restrict__ bias) {
    __shared__ float As[16][PAD];   // k-major: As[k][m_local]
    __shared__ float Bs[16][PAD];   // k-major: Bs[k][e_local]
    const int t  = threadIdx.x;
    const int tx = t & 15;
    const int ty = t >> 4;
    const int m0 = blockIdx.y * 64;
    const int e0 = blockIdx.x * 64;
    const int lr = t >> 2;          // 0..63
    const int lk = (t & 3) * 4;     // 0,4,8,12
    const float* Ap = A + (size_t)(m0 + lr) * DIM + lk;
    const float* Wp = W + (size_t)(e0 + lr) * DIM + lk;

    float acc[4][4] = {};
    for (int k0 = 0; k0 < DIM; k0 += 16) {
        float4 av = *(const float4*)(Ap + k0);
        float4 wv = *(const float4*)(Wp + k0);
        __syncthreads();
        As[lk+0][lr] = av.x; As[lk+1][lr] = av.y; As[lk+2][lr] = av.z; As[lk+3][lr] = av.w;
        Bs[lk+0][lr] = wv.x; Bs[lk+1][lr] = wv.y; Bs[lk+2][lr] = wv.z; Bs[lk+3][lr] = wv.w;
        __syncthreads();
#pragma unroll
        for (int kk = 0; kk < 16; kk++) {
            float4 a = *(const float4*)&As[kk][ty*4];
            float4 b = *(const float4*)&Bs[kk][tx*4];
            float ar[4] = {a.x, a.y, a.z, a.w};
            float br[4] = {b.x, b.y, b.z, b.w};
#pragma unroll
            for (int i = 0; i < 4; i++)
#pragma unroll
                for (int j = 0; j < 4; j++)
                    acc[i][j] = fmaf(ar[i], br[j], acc[i][j]);
        }
    }

    // Epilogue: this 64-wide column tile maps to exactly one (q/k/v, head)
    const int eb = e0 + tx * 4;
    const int s  = eb >> 10;              // 0=Q, 1=K, 2=V
    const int h  = (eb >> 6) & (HEADS-1);
    const int tc = eb & (HD-1);           // multiple of 4
    float4 bb = *(const float4*)(bias + eb);
    float* dst = (s == 0) ? g_Q : ((s == 1) ? g_K : g_V);
#pragma unroll
    for (int i = 0; i < 4; i++) {
        int m  = m0 + ty * 4 + i;
        int b_ = m >> 11;                 // /SEQ
        int n  = m & (SEQ - 1);
        float4 o;
        o.x = acc[i][0] + bb.x; o.y = acc[i][1] + bb.y;
        o.z = acc[i][2] + bb.z; o.w = acc[i][3] + bb.w;
        *(float4*)(dst + ((size_t)(b_ * HEADS + h) * SEQ + n) * HD + tc) = o;
    }
}

// ---------------------------------------------------------------------------
// Flash attention: one block per (b,h, 64-query tile). Online softmax.
// Shared: Qt[d][r] (scale folded), Kt[d][j], Vs[j][c], Ps[r][j], row stats.
//
// Tile loads: tiles are 64 rows x 64 dims = 4096 floats; 256 threads must
// each load FOUR float4s (d = lk + 16*c, c=0..3). (Round-8 bug: only one
// float4 per thread was loaded -> 3/4 of smem was stale -> rel_err 7.7.)
// ---------------------------------------------------------------------------
__global__ void __launch_bounds__(256) attn_fwd() {
    extern __shared__ float sm[];
    float* Qt   = sm;                 // [64][PAD], transposed: Qt[d][r]
    float* Kt   = Qt + 64 * PAD;      // [64][PAD], transposed: Kt[d][j]
    float* Vs   = Kt + 64 * PAD;      // [64][PAD], natural:    Vs[j][c]
    float* Ps   = Vs + 64 * PAD;      // [64][PAD], natural:    Ps[r][j]
    float* mrow = Ps + 64 * PAD;      // [64]
    float* lrow = mrow + 64;          // [64]
    float* arow = lrow + 64;          // [64]

    const int t  = threadIdx.x;
    const int tx = t & 15;
    const int ty = t >> 4;
    const int lr = t >> 2;            // 0..63 (row within tile)
    const int lk = (t & 3) * 4;       // 0,4,8,12 (base dim within 16-chunk)
    const int blk = blockIdx.x;
    const int qt  = blk & 31;         // query tile within sequence
    const int bh  = blk >> 5;         // b*HEADS + h
    const float* Qg = g_Q + (size_t)bh * SEQ * HD;
    const float* Kg = g_K + (size_t)bh * SEQ * HD;
    const float* Vg = g_V + (size_t)bh * SEQ * HD;
    const int q0 = qt * 64;
    const float scale = 0.125f;       // 1/sqrt(64)

    // Load full 64x64 Q tile, transposed, scale folded in.
#pragma unroll
    for (int c = 0; c < 4; c++) {
        int d = lk + 16 * c;
        float4 qv = *(const float4*)(Qg + (size_t)(q0 + lr) * HD + d);
        Qt[(d+0)*PAD + lr] = qv.x * scale;
        Qt[(d+1)*PAD + lr] = qv.y * scale;
        Qt[(d+2)*PAD + lr] = qv.z * scale;
        Qt[(d+3)*PAD + lr] = qv.w * scale;
    }
    if (t < 64) { mrow[t] = -1e30f; lrow[t] = 0.0f; }

    float o[4][4] = {};
    for (int j0 = 0; j0 < SEQ; j0 += 64) {
        // Fetch full 64x64 K and V tiles into registers before the sync.
        float4 kvr[4], vvr[4];
#pragma unroll
        for (int c = 0; c < 4; c++) {
            int d = lk + 16 * c;
            kvr[c] = *(const float4*)(Kg + (size_t)(j0 + lr) * HD + d);
            vvr[c] = *(const float4*)(Vg + (size_t)(j0 + lr) * HD + d);
        }
        __syncthreads();  // previous iter's Kt/Vs/Ps reads done
#pragma unroll
        for (int c = 0; c < 4; c++) {
            int d = lk + 16 * c;
            Kt[(d+0)*PAD + lr] = kvr[c].x;
            Kt[(d+1)*PAD + lr] = kvr[c].y;
            Kt[(d+2)*PAD + lr] = kvr[c].z;
            Kt[(d+3)*PAD + lr] = kvr[c].w;
            *(float4*)(Vs + lr * PAD + d) = vvr[c];
        }
        __syncthreads();

        // S = (Q*scale) K^T  -> Ps[r][j]
        float s[4][4] = {};
#pragma unroll 16
        for (int d = 0; d < HD; d++) {
            float4 qa = *(const float4*)(Qt + d * PAD + ty * 4);
            float4 kb = *(const float4*)(Kt + d * PAD + tx * 4);
            float ar[4] = {qa.x, qa.y, qa.z, qa.w};
            float br[4] = {kb.x, kb.y, kb.z, kb.w};
#pragma unroll
            for (int i = 0; i < 4; i++)
#pragma unroll
                for (int j = 0; j < 4; j++)
                    s[i][j] = fmaf(ar[i], br[j], s[i][j]);
        }
#pragma unroll
        for (int i = 0; i < 4; i++) {
            float4 sv; sv.x = s[i][0]; sv.y = s[i][1]; sv.z = s[i][2]; sv.w = s[i][3];
            *(float4*)(Ps + (ty * 4 + i) * PAD + tx * 4) = sv;
        }
        __syncthreads();

        // Online softmax: 4 threads per row, shfl reduce within lane-groups of 4.
        {
            const int r = t >> 2;
            const int q = t & 3;
            float mold = mrow[r];
            float mx = -1e30f;
#pragma unroll
            for (int k = 0; k < 16; k++)
                mx = fmaxf(mx, Ps[r * PAD + q * 16 + k]);
            mx = fmaxf(mx, __shfl_xor_sync(0xffffffffu, mx, 1));
            mx = fmaxf(mx, __shfl_xor_sync(0xffffffffu, mx, 2));
            float mn = fmaxf(mold, mx);
            float ssum = 0.0f;
#pragma unroll
            for (int k = 0; k < 16; k++) {
                float p = __expf(Ps[r * PAD + q * 16 + k] - mn);
                Ps[r * PAD + q * 16 + k] = p;
                ssum += p;
            }
            ssum += __shfl_xor_sync(0xffffffffu, ssum, 1);
            ssum += __shfl_xor_sync(0xffffffffu, ssum, 2);
            if (q == 0) {
                float alpha = __expf(mold - mn);
                arow[r] = alpha;
                lrow[r] = lrow[r] * alpha + ssum;
                mrow[r] = mn;
            }
        }
        __syncthreads();

        // Rescale accumulator, then O += P * V
#pragma unroll
        for (int i = 0; i < 4; i++) {
            float al = arow[ty * 4 + i];
            o[i][0] *= al; o[i][1] *= al; o[i][2] *= al; o[i][3] *= al;
        }
#pragma unroll 16
        for (int jj = 0; jj < 64; jj++) {
            float4 vb = *(const float4*)(Vs + jj * PAD + tx * 4);
            float vr[4] = {vb.x, vb.y, vb.z, vb.w};
#pragma unroll
            for (int i = 0; i < 4; i++) {
                float p = Ps[(ty * 4 + i) * PAD + jj];   // broadcast within half-warp
#pragma unroll
                for (int c = 0; c < 4; c++)
                    o[i][c] = fmaf(p, vr[c], o[i][c]);
            }
        }
    }

    // Finalize: divide by l, write to [B,N,D] (heads re-interleaved)
    const int b_ = bh >> 4;
    const int h  = bh & (HEADS - 1);
#pragma unroll
    for (int i = 0; i < 4; i++) {
        int r = ty * 4 + i;
        float inv = 1.0f / lrow[r];
        float4 ov;
        ov.x = o[i][0] * inv; ov.y = o[i][1] * inv;
        ov.z = o[i][2] * inv; ov.w = o[i][3] * inv;
        *(float4*)(g_AO + (size_t)(b_ * SEQ + q0 + r) * DIM + h * HD + tx * 4) = ov;
    }
}

// ---------------------------------------------------------------------------
// Output projection: out[m,e] = sum_k AO[m,k] * W_out[e,k] + b_out[e]
// ---------------------------------------------------------------------------
__global__ void __launch_bounds__(256) out_gemm(const float* __restrict__ W,
                                                const float* __restrict__ bias,
                                                float* __restrict__ C) {
    __shared__ float As[16][PAD];
    __shared__ float Bs[16][PAD];
    const int t  = threadIdx.x;
    const int tx = t & 15;
    const int ty = t >> 4;
    const int m0 = blockIdx.y * 64;
    const int e0 = blockIdx.x * 64;
    const int lr = t >> 2;
    const int lk = (t & 3) * 4;
    const float* Ap = g_AO + (size_t)(m0 + lr) * DIM + lk;
    const float* Wp = W    + (size_t)(e0 + lr) * DIM + lk;

    float acc[4][4] = {};
    for (int k0 = 0; k0 < DIM; k0 += 16) {
        float4 av = *(const float4*)(Ap + k0);
        float4 wv = *(const float4*)(Wp + k0);
        __syncthreads();
        As[lk+0][lr] = av.x; As[lk+1][lr] = av.y; As[lk+2][lr] = av.z; As[lk+3][lr] = av.w;
        Bs[lk+0][lr] = wv.x; Bs[lk+1][lr] = wv.y; Bs[lk+2][lr] = wv.z; Bs[lk+3][lr] = wv.w;
        __syncthreads();
#pragma unroll
        for (int kk = 0; kk < 16; kk++) {
            float4 a = *(const float4*)&As[kk][ty*4];
            float4 b = *(const float4*)&Bs[kk][tx*4];
            float ar[4] = {a.x, a.y, a.z, a.w};
            float br[4] = {b.x, b.y, b.z, b.w};
#pragma unroll
            for (int i = 0; i < 4; i++)
#pragma unroll
                for (int j = 0; j < 4; j++)
                    acc[i][j] = fmaf(ar[i], br[j], acc[i][j]);
        }
    }

    const int eb = e0 + tx * 4;
    float4 bb = *(const float4*)(bias + eb);
#pragma unroll
    for (int i = 0; i < 4; i++) {
        int m = m0 + ty * 4 + i;
        float4 ov;
        ov.x = acc[i][0] + bb.x; ov.y = acc[i][1] + bb.y;
        ov.z = acc[i][2] + bb.z; ov.w = acc[i][3] + bb.w;
        *(float4*)(C + (size_t)m * DIM + eb) = ov;
    }
}

// ---------------------------------------------------------------------------
extern "C" void kernel_launch(void* const* d_in, const int* in_sizes, int n_in,
                              void* d_out, int out_size) {
    const float* x     = (const float*)d_in[0];
    const float* W_qkv = (const float*)d_in[1];
    const float* b_qkv = (const float*)d_in[2];
    const float* W_out = (const float*)d_in[3];
    const float* b_out = (const float*)d_in[4];
    float* out = (float*)d_out;

    // 1) QKV projection, scattered into per-head Q/K/V
    qkv_gemm<<<dim3(EQKV / 64, MTOT / 64), 256>>>(x, W_qkv, b_qkv);

    // 2) Flash attention (dynamic smem > 48KB needs opt-in; host-side attribute
    //    set, safe under graph capture, no allocation)
    const int smem_bytes = (4 * 64 * PAD + 3 * 64) * (int)sizeof(float);  // 70400
    cudaFuncSetAttribute(attn_fwd, cudaFuncAttributeMaxDynamicSharedMemorySize, smem_bytes);
    attn_fwd<<<BATCH * HEADS * (SEQ / 64), 256, smem_bytes>>>();

    // 3) Output projection
    out_gemm<<<dim3(DIM / 64, MTOT / 64), 256>>>(W_out, b_out, out);
}

// round 12
// speedup vs baseline: 1.2276x; 1.2276x over previous
#include <cuda_runtime.h>
#include <math.h>

#define BATCH 2
#define SEQ   2048
#define DIM   1024
#define HEADS 16
#define HD    64
#define MTOT  (BATCH*SEQ)     // 4096
#define EQKV  (3*DIM)         // 3072
#define PAD   68              // attn smem row stride (floats)
#define SW    132             // gemm smem row stride (floats)

typedef unsigned long long ull;

// Scratch (allocation-free rule: __device__ globals).
// NOTE: these may ONLY be referenced from device code. Passing them as kernel
// arguments from host code passes the host-side shadow address (the rounds
// 10/11 bug: rel_err 0.6077 from out-proj reading garbage).
__device__ float g_Q[BATCH*HEADS*SEQ*HD];   // [B,H,N,hd]
__device__ float g_K[BATCH*HEADS*SEQ*HD];
__device__ float g_V[BATCH*HEADS*SEQ*HD];
__device__ float g_AO[(size_t)MTOT*DIM];    // attention output, [B,N,D]

// ---- packed f32x2 helpers (bitwise == two fma.rn; dual-rate fp32 pipe) ----
__device__ __forceinline__ ull pk2(float lo, float hi) {
    ull r; asm("mov.b64 %0, {%1,%2};" : "=l"(r) : "f"(lo), "f"(hi)); return r;
}
__device__ __forceinline__ void upk2(float& lo, float& hi, ull v) {
    asm("mov.b64 {%0,%1}, %2;" : "=f"(lo), "=f"(hi) : "l"(v));
}
__device__ __forceinline__ void ffma2(ull& d, ull a, ull b) {
    asm("fma.rn.f32x2 %0, %1, %2, %0;" : "+l"(d) : "l"(a), "l"(b));
}
__device__ __forceinline__ void fmul2(ull& d, ull a) {
    asm("mul.rn.f32x2 %0, %0, %1;" : "+l"(d) : "l"(a));
}

// ---------------------------------------------------------------------------
// 128x128 GEMM, BK=16, 256 threads, 8x8 per thread, f32x2, double-buffered.
// C[m,e] = sum_k SRC[m,k] * W[e,k] + bias[e].
// QKV=1: SRC = A (harness x), scatter into g_Q/g_K/g_V ([B,H,N,hd]).
// QKV=0: SRC = g_AO (resolved IN DEVICE CODE), dense store to C.
// ---------------------------------------------------------------------------
template<int QKV>
__global__ void __launch_bounds__(256) gemm128(const float* __restrict__ A,
                                               const float* __restrict__ W,
                                               const float* __restrict__ bias,
                                               float* __restrict__ C) {
    extern __shared__ float sm[];
    float* AsBase = sm;               // [2][16][SW]
    float* BsBase = sm + 2 * 16 * SW; // [2][16][SW]

    const int t  = threadIdx.x;
    const int tx = t & 15;
    const int ty = t >> 4;
    const int lr = t >> 2;            // 0..63
    const int lk = (t & 3) * 4;       // 0,4,8,12
    const int m0 = blockIdx.y * 128;
    const int e0 = blockIdx.x * 128;

    const float* Asrc = QKV ? A : (const float*)g_AO;  // device-side resolution!
    const float* Ap  = Asrc + (size_t)(m0 + lr) * DIM + lk;
    const float* Ap2 = Ap + (size_t)64 * DIM;
    const float* Wp  = W + (size_t)(e0 + lr) * DIM + lk;
    const float* Wp2 = Wp + (size_t)64 * DIM;

    // Prologue: load slab 0 into buffer 0.
    float4 pa0 = *(const float4*)Ap,  pa1 = *(const float4*)Ap2;
    float4 pb0 = *(const float4*)Wp,  pb1 = *(const float4*)Wp2;
    {
        float* a = AsBase; float* b = BsBase;
        float av0[4] = {pa0.x,pa0.y,pa0.z,pa0.w}, av1[4] = {pa1.x,pa1.y,pa1.z,pa1.w};
        float bv0[4] = {pb0.x,pb0.y,pb0.z,pb0.w}, bv1[4] = {pb1.x,pb1.y,pb1.z,pb1.w};
#pragma unroll
        for (int i = 0; i < 4; i++) {
            a[(lk+i)*SW + lr]      = av0[i];
            a[(lk+i)*SW + lr + 64] = av1[i];
            b[(lk+i)*SW + lr]      = bv0[i];
            b[(lk+i)*SW + lr + 64] = bv1[i];
        }
    }
    __syncthreads();

    ull acc[8][2][2] = {};   // [row][col-half][pair]; zero bits == (0.f,0.f)
    int buf = 0;
    for (int k0 = 0; k0 < DIM; k0 += 16) {
        const bool more = (k0 + 16) < DIM;
        if (more) {
            pa0 = *(const float4*)(Ap  + k0 + 16);
            pa1 = *(const float4*)(Ap2 + k0 + 16);
            pb0 = *(const float4*)(Wp  + k0 + 16);
            pb1 = *(const float4*)(Wp2 + k0 + 16);
        }
        const float* a = AsBase + buf * 16 * SW;
        const float* b = BsBase + buf * 16 * SW;
#pragma unroll
        for (int kk = 0; kk < 16; kk++) {
            float4 a0 = *(const float4*)(a + kk*SW + ty*4);
            float4 a1 = *(const float4*)(a + kk*SW + ty*4 + 64);
            float4 b0 = *(const float4*)(b + kk*SW + tx*4);
            float4 b1 = *(const float4*)(b + kk*SW + tx*4 + 64);
            ull bp[2][2] = {{pk2(b0.x,b0.y), pk2(b0.z,b0.w)},
                            {pk2(b1.x,b1.y), pk2(b1.z,b1.w)}};
            float av[8] = {a0.x,a0.y,a0.z,a0.w, a1.x,a1.y,a1.z,a1.w};
#pragma unroll
            for (int i = 0; i < 8; i++) {
                ull ap = pk2(av[i], av[i]);
#pragma unroll
                for (int ch = 0; ch < 2; ch++) {
                    ffma2(acc[i][ch][0], ap, bp[ch][0]);
                    ffma2(acc[i][ch][1], ap, bp[ch][1]);
                }
            }
        }
        if (more) {
            float* a2 = AsBase + (buf^1) * 16 * SW;
            float* b2 = BsBase + (buf^1) * 16 * SW;
            float av0[4] = {pa0.x,pa0.y,pa0.z,pa0.w}, av1[4] = {pa1.x,pa1.y,pa1.z,pa1.w};
            float bv0[4] = {pb0.x,pb0.y,pb0.z,pb0.w}, bv1[4] = {pb1.x,pb1.y,pb1.z,pb1.w};
#pragma unroll
            for (int i = 0; i < 4; i++) {
                a2[(lk+i)*SW + lr]      = av0[i];
                a2[(lk+i)*SW + lr + 64] = av1[i];
                b2[(lk+i)*SW + lr]      = bv0[i];
                b2[(lk+i)*SW + lr + 64] = bv1[i];
            }
        }
        __syncthreads();
        buf ^= 1;
    }

    // Epilogue
    float4 bb[2] = {*(const float4*)(bias + e0 + tx*4),
                    *(const float4*)(bias + e0 + 64 + tx*4)};
#pragma unroll
    for (int i = 0; i < 8; i++) {
        const int m = m0 + ((i < 4) ? (ty*4 + i) : (64 + ty*4 + i - 4));
#pragma unroll
        for (int ch = 0; ch < 2; ch++) {
            const int e = e0 + ch*64 + tx*4;
            float4 o;
            upk2(o.x, o.y, acc[i][ch][0]);
            upk2(o.z, o.w, acc[i][ch][1]);
            const float4 bv = bb[ch];
            o.x += bv.x; o.y += bv.y; o.z += bv.z; o.w += bv.w;
            if (QKV) {
                const int s  = e >> 10;             // 0=Q,1=K,2=V
                const int h  = (e >> 6) & (HEADS-1);
                const int tc = e & (HD-1);
                float* dst = (s == 0) ? g_Q : ((s == 1) ? g_K : g_V);
                const int b_ = m >> 11;
                const int n  = m & (SEQ - 1);
                *(float4*)(dst + ((size_t)(b_ * HEADS + h) * SEQ + n) * HD + tc) = o;
            } else {
                *(float4*)(C + (size_t)m * DIM + e) = o;
            }
        }
    }
}

// ---------------------------------------------------------------------------
// Flash attention: one block per (b,h, 64-query tile). 256 threads, 4x4/thread.
// f32x2 math in S and PV. Softmax stats (m,l,alpha) in registers, reduced over
// the 16-lane row group via shfl_xor 1/2/4/8 (lane bit4 = ty parity, preserved).
// ---------------------------------------------------------------------------
__global__ void __launch_bounds__(256) attn_fwd() {
    extern __shared__ float sm[];
    float* Qt = sm;                 // [64][PAD], transposed: Qt[d][r], scale folded
    float* Kt = Qt + 64 * PAD;      // [64][PAD], transposed: Kt[d][j]
    float* Vs = Kt + 64 * PAD;      // [64][PAD], natural:    Vs[j][c]
    float* Ps = Vs + 64 * PAD;      // [64][PAD], natural:    Ps[r][j]

    const int t  = threadIdx.x;
    const int tx = t & 15;
    const int ty = t >> 4;
    const int lr = t >> 2;            // 0..63 (row within tile)
    const int lk = (t & 3) * 4;       // 0,4,8,12
    const int blk = blockIdx.x;
    const int qt  = blk & 31;
    const int bh  = blk >> 5;
    const float* Qg = g_Q + (size_t)bh * SEQ * HD;
    const float* Kg = g_K + (size_t)bh * SEQ * HD;
    const float* Vg = g_V + (size_t)bh * SEQ * HD;
    const int q0 = qt * 64;
    const float scale = 0.125f;       // 1/sqrt(64)

    // Full 64x64 Q tile, transposed, scale folded (4 float4 per thread).
#pragma unroll
    for (int c = 0; c < 4; c++) {
        int d = lk + 16 * c;
        float4 qv = *(const float4*)(Qg + (size_t)(q0 + lr) * HD + d);
        Qt[(d+0)*PAD + lr] = qv.x * scale;
        Qt[(d+1)*PAD + lr] = qv.y * scale;
        Qt[(d+2)*PAD + lr] = qv.z * scale;
        Qt[(d+3)*PAD + lr] = qv.w * scale;
    }

    float m_reg[4] = {-1e30f, -1e30f, -1e30f, -1e30f};
    float l_reg[4] = {0.f, 0.f, 0.f, 0.f};
    ull o2[4][2] = {};                 // 4 rows x 4 cols as 2 f32x2 pairs

    for (int j0 = 0; j0 < SEQ; j0 += 64) {
        // Fetch K/V tiles into registers before the sync.
        float4 kvr[4], vvr[4];
#pragma unroll
        for (int c = 0; c < 4; c++) {
            int d = lk + 16 * c;
            kvr[c] = *(const float4*)(Kg + (size_t)(j0 + lr) * HD + d);
            vvr[c] = *(const float4*)(Vg + (size_t)(j0 + lr) * HD + d);
        }
        __syncthreads();  // prior iter's Kt/Vs/Ps readers done
#pragma unroll
        for (int c = 0; c < 4; c++) {
            int d = lk + 16 * c;
            Kt[(d+0)*PAD + lr] = kvr[c].x;
            Kt[(d+1)*PAD + lr] = kvr[c].y;
            Kt[(d+2)*PAD + lr] = kvr[c].z;
            Kt[(d+3)*PAD + lr] = kvr[c].w;
            *(float4*)(Vs + lr * PAD + d) = vvr[c];
        }
        __syncthreads();

        // S = (Q*scale) K^T in f32x2 pairs
        ull s2[4][2] = {};
#pragma unroll 16
        for (int d = 0; d < HD; d++) {
            float4 qa = *(const float4*)(Qt + d * PAD + ty * 4);
            float4 kb = *(const float4*)(Kt + d * PAD + tx * 4);
            ull kb2[2] = {pk2(kb.x, kb.y), pk2(kb.z, kb.w)};
            float ar[4] = {qa.x, qa.y, qa.z, qa.w};
#pragma unroll
            for (int i = 0; i < 4; i++) {
                ull ap = pk2(ar[i], ar[i]);
                ffma2(s2[i][0], ap, kb2[0]);
                ffma2(s2[i][1], ap, kb2[1]);
            }
        }

        // Register online softmax per row (16-lane butterfly reductions).
#pragma unroll
        for (int i = 0; i < 4; i++) {
            float v0, v1, v2, v3;
            upk2(v0, v1, s2[i][0]);
            upk2(v2, v3, s2[i][1]);
            float mx = fmaxf(fmaxf(v0, v1), fmaxf(v2, v3));
            mx = fmaxf(mx, __shfl_xor_sync(0xffffffffu, mx, 1));
            mx = fmaxf(mx, __shfl_xor_sync(0xffffffffu, mx, 2));
            mx = fmaxf(mx, __shfl_xor_sync(0xffffffffu, mx, 4));
            mx = fmaxf(mx, __shfl_xor_sync(0xffffffffu, mx, 8));
            float mn = fmaxf(m_reg[i], mx);
            float p0 = __expf(v0 - mn), p1 = __expf(v1 - mn);
            float p2 = __expf(v2 - mn), p3 = __expf(v3 - mn);
            float ss = (p0 + p1) + (p2 + p3);
            ss += __shfl_xor_sync(0xffffffffu, ss, 1);
            ss += __shfl_xor_sync(0xffffffffu, ss, 2);
            ss += __shfl_xor_sync(0xffffffffu, ss, 4);
            ss += __shfl_xor_sync(0xffffffffu, ss, 8);
            float alpha = __expf(m_reg[i] - mn);
            l_reg[i] = l_reg[i] * alpha + ss;
            m_reg[i] = mn;
            ull al2 = pk2(alpha, alpha);
            fmul2(o2[i][0], al2);
            fmul2(o2[i][1], al2);
            float4 pv; pv.x = p0; pv.y = p1; pv.z = p2; pv.w = p3;
            *(float4*)(Ps + (ty * 4 + i) * PAD + tx * 4) = pv;
        }
        __syncthreads();  // Ps visible to all

        // O += P * V in f32x2 pairs
#pragma unroll 16
        for (int jj = 0; jj < 64; jj++) {
            float4 vb = *(const float4*)(Vs + jj * PAD + tx * 4);
            ull vb2[2] = {pk2(vb.x, vb.y), pk2(vb.z, vb.w)};
#pragma unroll
            for (int i = 0; i < 4; i++) {
                float p = Ps[(ty * 4 + i) * PAD + jj];   // broadcast in row group
                ull pp = pk2(p, p);
                ffma2(o2[i][0], pp, vb2[0]);
                ffma2(o2[i][1], pp, vb2[1]);
            }
        }
    }

    // Finalize: divide by l, write [B,N,D] (heads re-interleaved)
    const int b_ = bh >> 4;
    const int h  = bh & (HEADS - 1);
#pragma unroll
    for (int i = 0; i < 4; i++) {
        const int r = ty * 4 + i;
        const float inv = 1.0f / l_reg[i];
        float4 ov;
        upk2(ov.x, ov.y, o2[i][0]);
        upk2(ov.z, ov.w, o2[i][1]);
        ov.x *= inv; ov.y *= inv; ov.z *= inv; ov.w *= inv;
        *(float4*)(g_AO + (size_t)(b_ * SEQ + q0 + r) * DIM + h * HD + tx * 4) = ov;
    }
}

// ---------------------------------------------------------------------------
extern "C" void kernel_launch(void* const* d_in, const int* in_sizes, int n_in,
                              void* d_out, int out_size) {
    const float* x     = (const float*)d_in[0];
    const float* W_qkv = (const float*)d_in[1];
    const float* b_qkv = (const float*)d_in[2];
    const float* W_out = (const float*)d_in[3];
    const float* b_out = (const float*)d_in[4];
    float* out = (float*)d_out;

    const int gemm_smem = 2 * 2 * 16 * SW * (int)sizeof(float);  // 67584
    cudaFuncSetAttribute(gemm128<1>, cudaFuncAttributeMaxDynamicSharedMemorySize, gemm_smem);
    cudaFuncSetAttribute(gemm128<0>, cudaFuncAttributeMaxDynamicSharedMemorySize, gemm_smem);

    // 1) QKV projection (scatter into per-head Q/K/V)
    gemm128<1><<<dim3(EQKV / 128, MTOT / 128), 256, gemm_smem>>>(x, W_qkv, b_qkv, nullptr);

    // 2) Flash attention
    const int attn_smem = 4 * 64 * PAD * (int)sizeof(float);  // 69632
    cudaFuncSetAttribute(attn_fwd, cudaFuncAttributeMaxDynamicSharedMemorySize, attn_smem);
    attn_fwd<<<BATCH * HEADS * (SEQ / 64), 256, attn_smem>>>();

    // 3) Output projection (reads g_AO from device code; A arg unused)
    gemm128<0><<<dim3(DIM / 128, MTOT / 128), 256, gemm_smem>>>(nullptr, W_out, b_out, out);
}

// round 15
// speedup vs baseline: 1.4678x; 1.1957x over previous
#include <cuda_runtime.h>
#include <cuda_bf16.h>
#include <math.h>
#include <stdint.h>

#define BATCH 2
#define SEQ   2048
#define DIM   1024
#define HEADS 16
#define HD    64
#define MTOT  (BATCH*SEQ)     // 4096
#define EQKV  (3*DIM)         // 3072
#define PAD   68              // attn smem row stride (floats)
#define LDT   40              // gemm smem row stride (bf16): 80B rows

typedef unsigned long long ull;

// ---------------------------------------------------------------------------
// Scratch (__device__ globals; allocation-free rule).
// HOUSE RULE: never pass these as kernel args from host (host sees the shadow
// symbol address — rounds-10/11 bug). Always resolve inside device code.
// ---------------------------------------------------------------------------
__device__ float g_Q[BATCH*HEADS*SEQ*HD];   // [B,H,N,hd] fp32
__device__ float g_K[BATCH*HEADS*SEQ*HD];
__device__ float g_V[BATCH*HEADS*SEQ*HD];
__device__ float g_AO[(size_t)MTOT*DIM];    // attention output [B,N,D] fp32

__device__ __nv_bfloat16 g_xhi[(size_t)MTOT*DIM],  g_xlo[(size_t)MTOT*DIM];
__device__ __nv_bfloat16 g_wqh[(size_t)EQKV*DIM],  g_wql[(size_t)EQKV*DIM];
__device__ __nv_bfloat16 g_woh[(size_t)DIM*DIM],   g_wol[(size_t)DIM*DIM];
__device__ __nv_bfloat16 g_aoh[(size_t)MTOT*DIM],  g_aol[(size_t)MTOT*DIM];

// ---- packed f32x2 helpers (dual-rate fp32 pipe) ----
__device__ __forceinline__ ull pk2(float lo, float hi) {
    ull r; asm("mov.b64 %0, {%1,%2};" : "=l"(r) : "f"(lo), "f"(hi)); return r;
}
__device__ __forceinline__ void upk2(float& lo, float& hi, ull v) {
    asm("mov.b64 {%0,%1}, %2;" : "=f"(lo), "=f"(hi) : "l"(v));
}
__device__ __forceinline__ void ffma2(ull& d, ull a, ull b) {
    asm("fma.rn.f32x2 %0, %1, %2, %0;" : "+l"(d) : "l"(a), "l"(b));
}
__device__ __forceinline__ void fmul2(ull& d, ull a) {
    asm("mul.rn.f32x2 %0, %0, %1;" : "+l"(d) : "l"(a));
}

// ---- base-ISA tensor core helpers (valid on PTX target sm_103) ----
__device__ __forceinline__ uint32_t smem_u32(const void* p) {
    uint32_t a;
    asm("{ .reg .u64 t; cvta.to.shared.u64 t, %1; cvt.u32.u64 %0, t; }" : "=r"(a) : "l"(p));
    return a;
}
__device__ __forceinline__ void ldm_x4(uint32_t* r, uint32_t addr) {
    asm volatile("ldmatrix.sync.aligned.m8n8.x4.shared.b16 {%0,%1,%2,%3}, [%4];"
        : "=r"(r[0]), "=r"(r[1]), "=r"(r[2]), "=r"(r[3]) : "r"(addr));
}
__device__ __forceinline__ void mma16816(float* c, const uint32_t* a, const uint32_t* b) {
    asm volatile("mma.sync.aligned.m16n8k16.row.col.f32.bf16.bf16.f32 "
        "{%0,%1,%2,%3}, {%4,%5,%6,%7}, {%8,%9}, {%0,%1,%2,%3};"
        : "+f"(c[0]), "+f"(c[1]), "+f"(c[2]), "+f"(c[3])
        : "r"(a[0]), "r"(a[1]), "r"(a[2]), "r"(a[3]), "r"(b[0]), "r"(b[1]));
}

// ---------------------------------------------------------------------------
// fp32 -> bf16 hi/lo split. Destinations resolved IN DEVICE CODE.
// W: 0 = x, 1 = W_qkv, 2 = W_out, 3 = g_AO (src param ignored).
// ---------------------------------------------------------------------------
template<int W>
__global__ void __launch_bounds__(256) cvt_split(const float* __restrict__ srcp, int n) {
    const float* src = (W == 3) ? (const float*)g_AO : srcp;
    __nv_bfloat16 *hi, *lo;
    if      (W == 0) { hi = g_xhi; lo = g_xlo; }
    else if (W == 1) { hi = g_wqh; lo = g_wql; }
    else if (W == 2) { hi = g_woh; lo = g_wol; }
    else             { hi = g_aoh; lo = g_aol; }
    int i = (blockIdx.x * blockDim.x + threadIdx.x) * 4;
    if (i >= n) return;
    float4 v = *(const float4*)(src + i);
    __nv_bfloat16 h0 = __float2bfloat16(v.x), h1 = __float2bfloat16(v.y);
    __nv_bfloat16 h2 = __float2bfloat16(v.z), h3 = __float2bfloat16(v.w);
    __nv_bfloat16 l0 = __float2bfloat16(v.x - __bfloat162float(h0));
    __nv_bfloat16 l1 = __float2bfloat16(v.y - __bfloat162float(h1));
    __nv_bfloat16 l2 = __float2bfloat16(v.z - __bfloat162float(h2));
    __nv_bfloat16 l3 = __float2bfloat16(v.w - __bfloat162float(h3));
    *(__nv_bfloat162*)(hi + i)     = __halves2bfloat162(h0, h1);
    *(__nv_bfloat162*)(hi + i + 2) = __halves2bfloat162(h2, h3);
    *(__nv_bfloat162*)(lo + i)     = __halves2bfloat162(l0, l1);
    *(__nv_bfloat162*)(lo + i + 2) = __halves2bfloat162(l2, l3);
}

// ---------------------------------------------------------------------------
// Tensor-core GEMM via mma.sync (HMMA), split-bf16 3-pass, fp32 accum.
// C[m,e] = sum_k SRC[m,k] * W[e,k] + bias[e].
// Block 128x128, BK=32, 256 threads = 8 warps (warp tile 32x64).
// Double-buffered smem: [2][Ah,Al,Bh,Bl][128][LDT] bf16.
// B operand: W stored [n][k] -> consecutive-k pairs for fixed n -> NON-trans
// ldmatrix gives exactly the b0/b1 fragment map (round-14 bug was .trans).
// ---------------------------------------------------------------------------
template<int QKV>
__global__ void __launch_bounds__(256) gemm_mma(const float* __restrict__ bias,
                                               float* __restrict__ Cout) {
    extern __shared__ __align__(16) __nv_bfloat16 smb[];
    const int TILE = 128 * LDT;              // 5120 bf16 per tile
    const uint32_t ub = smem_u32(smb);

    const int t = threadIdx.x;
    const int wid = t >> 5, lane = t & 31;
    const int wm = wid >> 1, wn = wid & 1;
    const int m0 = blockIdx.y * 128, e0 = blockIdx.x * 128;

    const __nv_bfloat16* Ahp = QKV ? g_xhi : g_aoh;
    const __nv_bfloat16* Alp = QKV ? g_xlo : g_aol;
    const __nv_bfloat16* Bhp = QKV ? g_wqh : g_woh;
    const __nv_bfloat16* Blp = QKV ? g_wql : g_wol;

    // Loader: thread t handles row lrow = t>>1, bf16 cols [lu*8, lu*8+16).
    const int lrow = t >> 1;
    const int lu   = (t & 1) * 2;
    const __nv_bfloat16* gAh = Ahp + (size_t)(m0 + lrow) * DIM + lu * 8;
    const __nv_bfloat16* gAl = Alp + (size_t)(m0 + lrow) * DIM + lu * 8;
    const __nv_bfloat16* gBh = Bhp + (size_t)(e0 + lrow) * DIM + lu * 8;
    const __nv_bfloat16* gBl = Blp + (size_t)(e0 + lrow) * DIM + lu * 8;

    uint4 pf[4][2];
#define FETCH(k0) do { \
        pf[0][0] = *(const uint4*)(gAh + (k0));     pf[0][1] = *(const uint4*)(gAh + (k0) + 8); \
        pf[1][0] = *(const uint4*)(gAl + (k0));     pf[1][1] = *(const uint4*)(gAl + (k0) + 8); \
        pf[2][0] = *(const uint4*)(gBh + (k0));     pf[2][1] = *(const uint4*)(gBh + (k0) + 8); \
        pf[3][0] = *(const uint4*)(gBl + (k0));     pf[3][1] = *(const uint4*)(gBl + (k0) + 8); \
    } while (0)
#define STORE(bufi) do { \
        __nv_bfloat16* d = smb + (bufi) * 4 * TILE + lrow * LDT + lu * 8; \
        *(uint4*)(d)                 = pf[0][0];  *(uint4*)(d + 8)            = pf[0][1]; \
        *(uint4*)(d + TILE)          = pf[1][0];  *(uint4*)(d + TILE + 8)     = pf[1][1]; \
        *(uint4*)(d + 2*TILE)        = pf[2][0];  *(uint4*)(d + 2*TILE + 8)   = pf[2][1]; \
        *(uint4*)(d + 3*TILE)        = pf[3][0];  *(uint4*)(d + 3*TILE + 8)   = pf[3][1]; \
    } while (0)

    FETCH(0);
    STORE(0);
    __syncthreads();

    float acc[2][8][4];
#pragma unroll
    for (int i = 0; i < 2; i++)
#pragma unroll
        for (int j = 0; j < 8; j++)
#pragma unroll
            for (int k = 0; k < 4; k++) acc[i][j][k] = 0.f;

    int buf = 0;
    for (int c = 0; c < 32; c++) {
        if (c < 31) FETCH((c + 1) * 32);
        const uint32_t sb = ub + (uint32_t)buf * 4 * TILE * 2;
#pragma unroll
        for (int ks = 0; ks < 2; ks++) {
            // A fragments (hi, lo) for 2 m-tiles (non-trans; rows m, cols k)
            uint32_t fa[2][2][4];
#pragma unroll
            for (int mt = 0; mt < 2; mt++) {
                const int row = wm * 32 + mt * 16 + (lane & 15);
                const int col = ks * 16 + (lane >> 4) * 8;
                const uint32_t off = (uint32_t)(row * LDT + col) * 2;
                ldm_x4(fa[0][mt], sb + off);
                ldm_x4(fa[1][mt], sb + (uint32_t)TILE * 2 + off);
            }
            // B fragments (hi, lo) for 8 n-tiles. NON-trans: W rows are n,
            // cols are k; lanes 0-7 -> n@k, 8-15 -> n@k+8, 16-23 -> n+8@k,
            // 24-31 -> n+8@k+8. r0/r1 = (b0,b1) of n-tile 2pq, r2/r3 of 2pq+1.
            uint32_t fb[2][8][2];
#pragma unroll
            for (int pq = 0; pq < 4; pq++) {
                const int nr = wn * 64 + pq * 16 + ((lane >> 4) & 1) * 8 + (lane & 7);
                const int kc = ks * 16 + ((lane >> 3) & 1) * 8;
                const uint32_t off = (uint32_t)(nr * LDT + kc) * 2;
                uint32_t r[4];
                ldm_x4(r, sb + (uint32_t)(2 * TILE) * 2 + off);
                fb[0][2*pq][0] = r[0]; fb[0][2*pq][1] = r[1];
                fb[0][2*pq+1][0] = r[2]; fb[0][2*pq+1][1] = r[3];
                ldm_x4(r, sb + (uint32_t)(3 * TILE) * 2 + off);
                fb[1][2*pq][0] = r[0]; fb[1][2*pq][1] = r[1];
                fb[1][2*pq+1][0] = r[2]; fb[1][2*pq+1][1] = r[3];
            }
            // 3-pass split: hi*hi + hi*lo + lo*hi
#pragma unroll
            for (int mt = 0; mt < 2; mt++)
#pragma unroll
                for (int nt = 0; nt < 8; nt++) {
                    mma16816(acc[mt][nt], fa[0][mt], fb[0][nt]);
                    mma16816(acc[mt][nt], fa[0][mt], fb[1][nt]);
                    mma16816(acc[mt][nt], fa[1][mt], fb[0][nt]);
                }
        }
        if (c < 31) STORE(buf ^ 1);
        __syncthreads();
        buf ^= 1;
    }

    // Epilogue: c0:(r,c) c1:(r,c+1) c2:(r+8,c) c3:(r+8,c+1); r=lane>>2, c=(lane&3)*2
#pragma unroll
    for (int mt = 0; mt < 2; mt++) {
        const int mbase = m0 + wm * 32 + mt * 16 + (lane >> 2);
#pragma unroll
        for (int nt = 0; nt < 8; nt++) {
            const int e = e0 + wn * 64 + nt * 8 + (lane & 3) * 2;
            const float bx = __ldg(bias + e), by = __ldg(bias + e + 1);
#pragma unroll
            for (int rh = 0; rh < 2; rh++) {
                const int m = mbase + rh * 8;
                const float vx = acc[mt][nt][rh * 2 + 0] + bx;
                const float vy = acc[mt][nt][rh * 2 + 1] + by;
                if (QKV) {
                    const int s  = e >> 10;             // 0=Q,1=K,2=V
                    const int h  = (e >> 6) & (HEADS - 1);
                    const int tc = e & (HD - 1);
                    float* dst = (s == 0) ? g_Q : ((s == 1) ? g_K : g_V);
                    const int b_ = m >> 11;
                    const int n  = m & (SEQ - 1);
                    *(float2*)(dst + ((size_t)(b_ * HEADS + h) * SEQ + n) * HD + tc) =
                        make_float2(vx, vy);
                } else {
                    *(float2*)(Cout + (size_t)m * DIM + e) = make_float2(vx, vy);
                }
            }
        }
    }
#undef FETCH
#undef STORE
}

// ---------------------------------------------------------------------------
// Flash attention (round-12 proven): one block per (b,h, 64-query tile),
// 256 threads, 4x4/thread, f32x2 math, register softmax w/ shfl reductions.
// ---------------------------------------------------------------------------
__global__ void __launch_bounds__(256) attn_fwd() {
    extern __shared__ float sm[];
    float* Qt = sm;                 // [64][PAD] transposed, scale folded
    float* Kt = Qt + 64 * PAD;      // [64][PAD] transposed
    float* Vs = Kt + 64 * PAD;      // [64][PAD] natural
    float* Ps = Vs + 64 * PAD;      // [64][PAD] natural

    const int t  = threadIdx.x;
    const int tx = t & 15;
    const int ty = t >> 4;
    const int lr = t >> 2;
    const int lk = (t & 3) * 4;
    const int blk = blockIdx.x;
    const int qt  = blk & 31;
    const int bh  = blk >> 5;
    const float* Qg = g_Q + (size_t)bh * SEQ * HD;
    const float* Kg = g_K + (size_t)bh * SEQ * HD;
    const float* Vg = g_V + (size_t)bh * SEQ * HD;
    const int q0 = qt * 64;
    const float scale = 0.125f;

#pragma unroll
    for (int c = 0; c < 4; c++) {
        int d = lk + 16 * c;
        float4 qv = *(const float4*)(Qg + (size_t)(q0 + lr) * HD + d);
        Qt[(d+0)*PAD + lr] = qv.x * scale;
        Qt[(d+1)*PAD + lr] = qv.y * scale;
        Qt[(d+2)*PAD + lr] = qv.z * scale;
        Qt[(d+3)*PAD + lr] = qv.w * scale;
    }

    float m_reg[4] = {-1e30f, -1e30f, -1e30f, -1e30f};
    float l_reg[4] = {0.f, 0.f, 0.f, 0.f};
    ull o2[4][2] = {};

    for (int j0 = 0; j0 < SEQ; j0 += 64) {
        float4 kvr[4], vvr[4];
#pragma unroll
        for (int c = 0; c < 4; c++) {
            int d = lk + 16 * c;
            kvr[c] = *(const float4*)(Kg + (size_t)(j0 + lr) * HD + d);
            vvr[c] = *(const float4*)(Vg + (size_t)(j0 + lr) * HD + d);
        }
        __syncthreads();
#pragma unroll
        for (int c = 0; c < 4; c++) {
            int d = lk + 16 * c;
            Kt[(d+0)*PAD + lr] = kvr[c].x;
            Kt[(d+1)*PAD + lr] = kvr[c].y;
            Kt[(d+2)*PAD + lr] = kvr[c].z;
            Kt[(d+3)*PAD + lr] = kvr[c].w;
            *(float4*)(Vs + lr * PAD + d) = vvr[c];
        }
        __syncthreads();

        ull s2[4][2] = {};
#pragma unroll 16
        for (int d = 0; d < HD; d++) {
            float4 qa = *(const float4*)(Qt + d * PAD + ty * 4);
            float4 kb = *(const float4*)(Kt + d * PAD + tx * 4);
            ull kb2[2] = {pk2(kb.x, kb.y), pk2(kb.z, kb.w)};
            float ar[4] = {qa.x, qa.y, qa.z, qa.w};
#pragma unroll
            for (int i = 0; i < 4; i++) {
                ull ap = pk2(ar[i], ar[i]);
                ffma2(s2[i][0], ap, kb2[0]);
                ffma2(s2[i][1], ap, kb2[1]);
            }
        }

#pragma unroll
        for (int i = 0; i < 4; i++) {
            float v0, v1, v2, v3;
            upk2(v0, v1, s2[i][0]);
            upk2(v2, v3, s2[i][1]);
            float mx = fmaxf(fmaxf(v0, v1), fmaxf(v2, v3));
            mx = fmaxf(mx, __shfl_xor_sync(0xffffffffu, mx, 1));
            mx = fmaxf(mx, __shfl_xor_sync(0xffffffffu, mx, 2));
            mx = fmaxf(mx, __shfl_xor_sync(0xffffffffu, mx, 4));
            mx = fmaxf(mx, __shfl_xor_sync(0xffffffffu, mx, 8));
            float mn = fmaxf(m_reg[i], mx);
            float p0 = __expf(v0 - mn), p1 = __expf(v1 - mn);
            float p2 = __expf(v2 - mn), p3 = __expf(v3 - mn);
            float ss = (p0 + p1) + (p2 + p3);
            ss += __shfl_xor_sync(0xffffffffu, ss, 1);
            ss += __shfl_xor_sync(0xffffffffu, ss, 2);
            ss += __shfl_xor_sync(0xffffffffu, ss, 4);
            ss += __shfl_xor_sync(0xffffffffu, ss, 8);
            float alpha = __expf(m_reg[i] - mn);
            l_reg[i] = l_reg[i] * alpha + ss;
            m_reg[i] = mn;
            ull al2 = pk2(alpha, alpha);
            fmul2(o2[i][0], al2);
            fmul2(o2[i][1], al2);
            float4 pv; pv.x = p0; pv.y = p1; pv.z = p2; pv.w = p3;
            *(float4*)(Ps + (ty * 4 + i) * PAD + tx * 4) = pv;
        }
        __syncthreads();

#pragma unroll 16
        for (int jj = 0; jj < 64; jj++) {
            float4 vb = *(const float4*)(Vs + jj * PAD + tx * 4);
            ull vb2[2] = {pk2(vb.x, vb.y), pk2(vb.z, vb.w)};
#pragma unroll
            for (int i = 0; i < 4; i++) {
                float p = Ps[(ty * 4 + i) * PAD + jj];
                ull pp = pk2(p, p);
                ffma2(o2[i][0], pp, vb2[0]);
                ffma2(o2[i][1], pp, vb2[1]);
            }
        }
    }

    const int b_ = bh >> 4;
    const int h  = bh & (HEADS - 1);
#pragma unroll
    for (int i = 0; i < 4; i++) {
        const int r = ty * 4 + i;
        const float inv = 1.0f / l_reg[i];
        float4 ov;
        upk2(ov.x, ov.y, o2[i][0]);
        upk2(ov.z, ov.w, o2[i][1]);
        ov.x *= inv; ov.y *= inv; ov.z *= inv; ov.w *= inv;
        *(float4*)(g_AO + (size_t)(b_ * SEQ + q0 + r) * DIM + h * HD + tx * 4) = ov;
    }
}

// ---------------------------------------------------------------------------
extern "C" void kernel_launch(void* const* d_in, const int* in_sizes, int n_in,
                              void* d_out, int out_size) {
    const float* x     = (const float*)d_in[0];
    const float* W_qkv = (const float*)d_in[1];
    const float* b_qkv = (const float*)d_in[2];
    const float* W_out = (const float*)d_in[3];
    const float* b_out = (const float*)d_in[4];
    float* out = (float*)d_out;

    const int n_x  = MTOT * DIM;     // 4194304
    const int n_wq = EQKV * DIM;     // 3145728
    const int n_wo = DIM * DIM;      // 1048576

    // 0) bf16 hi/lo splits of x and both weights
    cvt_split<0><<<n_x  / 1024, 256>>>(x,     n_x);
    cvt_split<1><<<n_wq / 1024, 256>>>(W_qkv, n_wq);
    cvt_split<2><<<n_wo / 1024, 256>>>(W_out, n_wo);

    // 1) QKV projection on tensor cores (HMMA), scattered into per-head Q/K/V
    const int gsmem = 2 * 4 * 128 * LDT * 2;   // 81920 B
    cudaFuncSetAttribute(gemm_mma<1>, cudaFuncAttributeMaxDynamicSharedMemorySize, gsmem);
    cudaFuncSetAttribute(gemm_mma<0>, cudaFuncAttributeMaxDynamicSharedMemorySize, gsmem);
    gemm_mma<1><<<dim3(EQKV / 128, MTOT / 128), 256, gsmem>>>(b_qkv, nullptr);

    // 2) Flash attention (fp32, f32x2)
    const int attn_smem = 4 * 64 * PAD * (int)sizeof(float);  // 69632
    cudaFuncSetAttribute(attn_fwd, cudaFuncAttributeMaxDynamicSharedMemorySize, attn_smem);
    attn_fwd<<<BATCH * HEADS * (SEQ / 64), 256, attn_smem>>>();

    // 3) AO -> bf16 hi/lo, then output projection on tensor cores
    cvt_split<3><<<n_x / 1024, 256>>>(nullptr, n_x);
    gemm_mma<0><<<dim3(DIM / 128, MTOT / 128), 256, gsmem>>>(b_out, out);
}

// round 16
// speedup vs baseline: 1.4718x; 1.0027x over previous
#include <cuda_runtime.h>
#include <cuda_bf16.h>
#include <math.h>
#include <stdint.h>

#define BATCH 2
#define SEQ   2048
#define DIM   1024
#define HEADS 16
#define HD    64
#define MTOT  (BATCH*SEQ)     // 4096
#define EQKV  (3*DIM)         // 3072
#define PAD   68              // attn smem row stride (floats)
#define LDT   40              // gemm smem row stride (bf16): 80B rows

typedef unsigned long long ull;

// ---------------------------------------------------------------------------
// Scratch (__device__ globals; allocation-free rule).
// HOUSE RULE: never pass these as kernel args from host — resolve in device code.
// ---------------------------------------------------------------------------
__device__ float g_Q[BATCH*HEADS*SEQ*HD];   // [B,H,N,hd] fp32
__device__ float g_K[BATCH*HEADS*SEQ*HD];
__device__ float g_V[BATCH*HEADS*SEQ*HD];
__device__ float g_AO[(size_t)MTOT*DIM];    // attention output [B,N,D] fp32

__device__ __nv_bfloat16 g_xhi[(size_t)MTOT*DIM],  g_xlo[(size_t)MTOT*DIM];
__device__ __nv_bfloat16 g_wqh[(size_t)EQKV*DIM],  g_wql[(size_t)EQKV*DIM];
__device__ __nv_bfloat16 g_woh[(size_t)DIM*DIM],   g_wol[(size_t)DIM*DIM];
__device__ __nv_bfloat16 g_aoh[(size_t)MTOT*DIM],  g_aol[(size_t)MTOT*DIM];

// ---- packed f32x2 helpers ----
__device__ __forceinline__ ull pk2(float lo, float hi) {
    ull r; asm("mov.b64 %0, {%1,%2};" : "=l"(r) : "f"(lo), "f"(hi)); return r;
}
__device__ __forceinline__ void upk2(float& lo, float& hi, ull v) {
    asm("mov.b64 {%0,%1}, %2;" : "=f"(lo), "=f"(hi) : "l"(v));
}
__device__ __forceinline__ void ffma2(ull& d, ull a, ull b) {
    asm("fma.rn.f32x2 %0, %1, %2, %0;" : "+l"(d) : "l"(a), "l"(b));
}
__device__ __forceinline__ void fmul2(ull& d, ull a) {
    asm("mul.rn.f32x2 %0, %0, %1;" : "+l"(d) : "l"(a));
}

// ---- FMA-pipe exp (replaces MUFU __expf; valid for x <= 0, clamped) ----
// exp(x) = 2^(x*log2e); poly 2^f on [-0.5,0.5] deg-6 (~1e-7 rel), exponent via
// integer bit injection. ~10 fixed-lat ops, no MUFU.
__device__ __forceinline__ float fexpf(float x) {
    x = fmaxf(x, -87.0f);
    const float y = x * 1.4426950408889634f;
    const float r = rintf(y);
    const float f = y - r;
    float p =            1.5403530e-4f;
    p = fmaf(p, f, 1.3333558e-3f);
    p = fmaf(p, f, 9.6181291e-3f);
    p = fmaf(p, f, 5.5504109e-2f);
    p = fmaf(p, f, 2.4022651e-1f);
    p = fmaf(p, f, 6.9314718e-1f);
    p = fmaf(p, f, 1.0f);
    const int e = (int)r;
    return __int_as_float(__float_as_int(p) + (e << 23));
}

// ---- base-ISA tensor core + cp.async helpers (PTX target sm_103-safe) ----
__device__ __forceinline__ uint32_t smem_u32(const void* p) {
    uint32_t a;
    asm("{ .reg .u64 t; cvta.to.shared.u64 t, %1; cvt.u32.u64 %0, t; }" : "=r"(a) : "l"(p));
    return a;
}
__device__ __forceinline__ void ldm_x4(uint32_t* r, uint32_t addr) {
    asm volatile("ldmatrix.sync.aligned.m8n8.x4.shared.b16 {%0,%1,%2,%3}, [%4];"
        : "=r"(r[0]), "=r"(r[1]), "=r"(r[2]), "=r"(r[3]) : "r"(addr));
}
__device__ __forceinline__ void mma16816(float* c, const uint32_t* a, const uint32_t* b) {
    asm volatile("mma.sync.aligned.m16n8k16.row.col.f32.bf16.bf16.f32 "
        "{%0,%1,%2,%3}, {%4,%5,%6,%7}, {%8,%9}, {%0,%1,%2,%3};"
        : "+f"(c[0]), "+f"(c[1]), "+f"(c[2]), "+f"(c[3])
        : "r"(a[0]), "r"(a[1]), "r"(a[2]), "r"(a[3]), "r"(b[0]), "r"(b[1]));
}
#define CPA16(dst, src) \
    asm volatile("cp.async.cg.shared.global [%0], [%1], 16;" :: "r"(dst), "l"(src) : "memory")
#define CPA_COMMIT() asm volatile("cp.async.commit_group;" ::: "memory")
#define CPA_WAIT1()  asm volatile("cp.async.wait_group 1;" ::: "memory")
#define CPA_WAIT0()  asm volatile("cp.async.wait_group 0;" ::: "memory")

// ---------------------------------------------------------------------------
// fp32 -> bf16 hi/lo split. Destinations resolved IN DEVICE CODE.
// ---------------------------------------------------------------------------
template<int W>
__global__ void __launch_bounds__(256) cvt_split(const float* __restrict__ srcp, int n) {
    const float* src = (W == 3) ? (const float*)g_AO : srcp;
    __nv_bfloat16 *hi, *lo;
    if      (W == 0) { hi = g_xhi; lo = g_xlo; }
    else if (W == 1) { hi = g_wqh; lo = g_wql; }
    else if (W == 2) { hi = g_woh; lo = g_wol; }
    else             { hi = g_aoh; lo = g_aol; }
    int i = (blockIdx.x * blockDim.x + threadIdx.x) * 4;
    if (i >= n) return;
    float4 v = *(const float4*)(src + i);
    __nv_bfloat16 h0 = __float2bfloat16(v.x), h1 = __float2bfloat16(v.y);
    __nv_bfloat16 h2 = __float2bfloat16(v.z), h3 = __float2bfloat16(v.w);
    __nv_bfloat16 l0 = __float2bfloat16(v.x - __bfloat162float(h0));
    __nv_bfloat16 l1 = __float2bfloat16(v.y - __bfloat162float(h1));
    __nv_bfloat16 l2 = __float2bfloat16(v.z - __bfloat162float(h2));
    __nv_bfloat16 l3 = __float2bfloat16(v.w - __bfloat162float(h3));
    *(__nv_bfloat162*)(hi + i)     = __halves2bfloat162(h0, h1);
    *(__nv_bfloat162*)(hi + i + 2) = __halves2bfloat162(h2, h3);
    *(__nv_bfloat162*)(lo + i)     = __halves2bfloat162(l0, l1);
    *(__nv_bfloat162*)(lo + i + 2) = __halves2bfloat162(l2, l3);
}

// ---------------------------------------------------------------------------
// Tensor-core GEMM (mma.sync), split-bf16 3-pass, fp32 accum.
// Round-16 changes: cp.async G->S (no register staging) + launch_bounds(,2)
// for 2 CTAs/SM. Compute core identical to proven round-15 version.
// ---------------------------------------------------------------------------
template<int QKV>
__global__ void __launch_bounds__(256, 2) gemm_mma(const float* __restrict__ bias,
                                                  float* __restrict__ Cout) {
    extern __shared__ __align__(16) __nv_bfloat16 smb[];
    const int TILE = 128 * LDT;              // 5120 bf16 per tile
    const uint32_t ub = smem_u32(smb);

    const int t = threadIdx.x;
    const int wid = t >> 5, lane = t & 31;
    const int wm = wid >> 1, wn = wid & 1;
    const int m0 = blockIdx.y * 128, e0 = blockIdx.x * 128;

    const __nv_bfloat16* Ahp = QKV ? g_xhi : g_aoh;
    const __nv_bfloat16* Alp = QKV ? g_xlo : g_aol;
    const __nv_bfloat16* Bhp = QKV ? g_wqh : g_woh;
    const __nv_bfloat16* Blp = QKV ? g_wql : g_wol;

    // Loader: thread t -> row lrow = t>>1, bf16 cols [lu*8, lu*8+16)
    const int lrow = t >> 1;
    const int lu   = (t & 1) * 2;
    const __nv_bfloat16* gAh = Ahp + (size_t)(m0 + lrow) * DIM + lu * 8;
    const __nv_bfloat16* gAl = Alp + (size_t)(m0 + lrow) * DIM + lu * 8;
    const __nv_bfloat16* gBh = Bhp + (size_t)(e0 + lrow) * DIM + lu * 8;
    const __nv_bfloat16* gBl = Blp + (size_t)(e0 + lrow) * DIM + lu * 8;
    const uint32_t so = (uint32_t)(lrow * LDT + lu * 8) * 2;   // byte offset in tile

#define PREF(k0, bufi) do { \
        const uint32_t d = ub + (uint32_t)(bufi) * 4u * TILE * 2u + so; \
        CPA16(d,                  gAh + (k0)); CPA16(d + 16,                  gAh + (k0) + 8); \
        CPA16(d + TILE*2,         gAl + (k0)); CPA16(d + TILE*2 + 16,         gAl + (k0) + 8); \
        CPA16(d + 2*TILE*2,       gBh + (k0)); CPA16(d + 2*TILE*2 + 16,       gBh + (k0) + 8); \
        CPA16(d + 3*TILE*2,       gBl + (k0)); CPA16(d + 3*TILE*2 + 16,       gBl + (k0) + 8); \
        CPA_COMMIT(); \
    } while (0)

    PREF(0, 0);

    float acc[2][8][4];
#pragma unroll
    for (int i = 0; i < 2; i++)
#pragma unroll
        for (int j = 0; j < 8; j++)
#pragma unroll
            for (int k = 0; k < 4; k++) acc[i][j][k] = 0.f;

    int buf = 0;
    for (int c = 0; c < 32; c++) {
        if (c < 31) { PREF((c + 1) * 32, buf ^ 1); CPA_WAIT1(); }
        else        { CPA_WAIT0(); }
        __syncthreads();                       // chunk c's data visible to all

        const uint32_t sb = ub + (uint32_t)buf * 4 * TILE * 2;
#pragma unroll
        for (int ks = 0; ks < 2; ks++) {
            // A fragments (hi, lo) for 2 m-tiles (non-trans)
            uint32_t fa[2][2][4];
#pragma unroll
            for (int mt = 0; mt < 2; mt++) {
                const int row = wm * 32 + mt * 16 + (lane & 15);
                const int col = ks * 16 + (lane >> 4) * 8;
                const uint32_t off = (uint32_t)(row * LDT + col) * 2;
                ldm_x4(fa[0][mt], sb + off);
                ldm_x4(fa[1][mt], sb + (uint32_t)TILE * 2 + off);
            }
            // B fragments (hi, lo), NON-trans on [n][k]-stored W
            uint32_t fb[2][8][2];
#pragma unroll
            for (int pq = 0; pq < 4; pq++) {
                const int nr = wn * 64 + pq * 16 + ((lane >> 4) & 1) * 8 + (lane & 7);
                const int kc = ks * 16 + ((lane >> 3) & 1) * 8;
                const uint32_t off = (uint32_t)(nr * LDT + kc) * 2;
                uint32_t r[4];
                ldm_x4(r, sb + (uint32_t)(2 * TILE) * 2 + off);
                fb[0][2*pq][0] = r[0]; fb[0][2*pq][1] = r[1];
                fb[0][2*pq+1][0] = r[2]; fb[0][2*pq+1][1] = r[3];
                ldm_x4(r, sb + (uint32_t)(3 * TILE) * 2 + off);
                fb[1][2*pq][0] = r[0]; fb[1][2*pq][1] = r[1];
                fb[1][2*pq+1][0] = r[2]; fb[1][2*pq+1][1] = r[3];
            }
            // 3-pass split: hi*hi + hi*lo + lo*hi
#pragma unroll
            for (int mt = 0; mt < 2; mt++)
#pragma unroll
                for (int nt = 0; nt < 8; nt++) {
                    mma16816(acc[mt][nt], fa[0][mt], fb[0][nt]);
                    mma16816(acc[mt][nt], fa[0][mt], fb[1][nt]);
                    mma16816(acc[mt][nt], fa[1][mt], fb[0][nt]);
                }
        }
        __syncthreads();                       // done reading buf before refill
        buf ^= 1;
    }

    // Epilogue: c0:(r,c) c1:(r,c+1) c2:(r+8,c) c3:(r+8,c+1); r=lane>>2, c=(lane&3)*2
#pragma unroll
    for (int mt = 0; mt < 2; mt++) {
        const int mbase = m0 + wm * 32 + mt * 16 + (lane >> 2);
#pragma unroll
        for (int nt = 0; nt < 8; nt++) {
            const int e = e0 + wn * 64 + nt * 8 + (lane & 3) * 2;
            const float bx = __ldg(bias + e), by = __ldg(bias + e + 1);
#pragma unroll
            for (int rh = 0; rh < 2; rh++) {
                const int m = mbase + rh * 8;
                const float vx = acc[mt][nt][rh * 2 + 0] + bx;
                const float vy = acc[mt][nt][rh * 2 + 1] + by;
                if (QKV) {
                    const int s  = e >> 10;             // 0=Q,1=K,2=V
                    const int h  = (e >> 6) & (HEADS - 1);
                    const int tc = e & (HD - 1);
                    float* dst = (s == 0) ? g_Q : ((s == 1) ? g_K : g_V);
                    const int b_ = m >> 11;
                    const int n  = m & (SEQ - 1);
                    *(float2*)(dst + ((size_t)(b_ * HEADS + h) * SEQ + n) * HD + tc) =
                        make_float2(vx, vy);
                } else {
                    *(float2*)(Cout + (size_t)m * DIM + e) = make_float2(vx, vy);
                }
            }
        }
    }
#undef PREF
}

// ---------------------------------------------------------------------------
// Flash attention: round-12 proven structure; __expf -> fexpf (off-MUFU).
// ---------------------------------------------------------------------------
__global__ void __launch_bounds__(256) attn_fwd() {
    extern __shared__ float sm[];
    float* Qt = sm;                 // [64][PAD] transposed, scale folded
    float* Kt = Qt + 64 * PAD;      // [64][PAD] transposed
    float* Vs = Kt + 64 * PAD;      // [64][PAD] natural
    float* Ps = Vs + 64 * PAD;      // [64][PAD] natural

    const int t  = threadIdx.x;
    const int tx = t & 15;
    const int ty = t >> 4;
    const int lr = t >> 2;
    const int lk = (t & 3) * 4;
    const int blk = blockIdx.x;
    const int qt  = blk & 31;
    const int bh  = blk >> 5;
    const float* Qg = g_Q + (size_t)bh * SEQ * HD;
    const float* Kg = g_K + (size_t)bh * SEQ * HD;
    const float* Vg = g_V + (size_t)bh * SEQ * HD;
    const int q0 = qt * 64;
    const float scale = 0.125f;

#pragma unroll
    for (int c = 0; c < 4; c++) {
        int d = lk + 16 * c;
        float4 qv = *(const float4*)(Qg + (size_t)(q0 + lr) * HD + d);
        Qt[(d+0)*PAD + lr] = qv.x * scale;
        Qt[(d+1)*PAD + lr] = qv.y * scale;
        Qt[(d+2)*PAD + lr] = qv.z * scale;
        Qt[(d+3)*PAD + lr] = qv.w * scale;
    }

    float m_reg[4] = {-1e30f, -1e30f, -1e30f, -1e30f};
    float l_reg[4] = {0.f, 0.f, 0.f, 0.f};
    ull o2[4][2] = {};

    for (int j0 = 0; j0 < SEQ; j0 += 64) {
        float4 kvr[4], vvr[4];
#pragma unroll
        for (int c = 0; c < 4; c++) {
            int d = lk + 16 * c;
            kvr[c] = *(const float4*)(Kg + (size_t)(j0 + lr) * HD + d);
            vvr[c] = *(const float4*)(Vg + (size_t)(j0 + lr) * HD + d);
        }
        __syncthreads();
#pragma unroll
        for (int c = 0; c < 4; c++) {
            int d = lk + 16 * c;
            Kt[(d+0)*PAD + lr] = kvr[c].x;
            Kt[(d+1)*PAD + lr] = kvr[c].y;
            Kt[(d+2)*PAD + lr] = kvr[c].z;
            Kt[(d+3)*PAD + lr] = kvr[c].w;
            *(float4*)(Vs + lr * PAD + d) = vvr[c];
        }
        __syncthreads();

        ull s2[4][2] = {};
#pragma unroll 16
        for (int d = 0; d < HD; d++) {
            float4 qa = *(const float4*)(Qt + d * PAD + ty * 4);
            float4 kb = *(const float4*)(Kt + d * PAD + tx * 4);
            ull kb2[2] = {pk2(kb.x, kb.y), pk2(kb.z, kb.w)};
            float ar[4] = {qa.x, qa.y, qa.z, qa.w};
#pragma unroll
            for (int i = 0; i < 4; i++) {
                ull ap = pk2(ar[i], ar[i]);
                ffma2(s2[i][0], ap, kb2[0]);
                ffma2(s2[i][1], ap, kb2[1]);
            }
        }

#pragma unroll
        for (int i = 0; i < 4; i++) {
            float v0, v1, v2, v3;
            upk2(v0, v1, s2[i][0]);
            upk2(v2, v3, s2[i][1]);
            float mx = fmaxf(fmaxf(v0, v1), fmaxf(v2, v3));
            mx = fmaxf(mx, __shfl_xor_sync(0xffffffffu, mx, 1));
            mx = fmaxf(mx, __shfl_xor_sync(0xffffffffu, mx, 2));
            mx = fmaxf(mx, __shfl_xor_sync(0xffffffffu, mx, 4));
            mx = fmaxf(mx, __shfl_xor_sync(0xffffffffu, mx, 8));
            float mn = fmaxf(m_reg[i], mx);
            float p0 = fexpf(v0 - mn), p1 = fexpf(v1 - mn);
            float p2 = fexpf(v2 - mn), p3 = fexpf(v3 - mn);
            float ss = (p0 + p1) + (p2 + p3);
            ss += __shfl_xor_sync(0xffffffffu, ss, 1);
            ss += __shfl_xor_sync(0xffffffffu, ss, 2);
            ss += __shfl_xor_sync(0xffffffffu, ss, 4);
            ss += __shfl_xor_sync(0xffffffffu, ss, 8);
            float alpha = fexpf(m_reg[i] - mn);
            l_reg[i] = l_reg[i] * alpha + ss;
            m_reg[i] = mn;
            ull al2 = pk2(alpha, alpha);
            fmul2(o2[i][0], al2);
            fmul2(o2[i][1], al2);
            float4 pv; pv.x = p0; pv.y = p1; pv.z = p2; pv.w = p3;
            *(float4*)(Ps + (ty * 4 + i) * PAD + tx * 4) = pv;
        }
        __syncthreads();

#pragma unroll 16
        for (int jj = 0; jj < 64; jj++) {
            float4 vb = *(const float4*)(Vs + jj * PAD + tx * 4);
            ull vb2[2] = {pk2(vb.x, vb.y), pk2(vb.z, vb.w)};
#pragma unroll
            for (int i = 0; i < 4; i++) {
                float p = Ps[(ty * 4 + i) * PAD + jj];
                ull pp = pk2(p, p);
                ffma2(o2[i][0], pp, vb2[0]);
                ffma2(o2[i][1], pp, vb2[1]);
            }
        }
    }

    const int b_ = bh >> 4;
    const int h  = bh & (HEADS - 1);
#pragma unroll
    for (int i = 0; i < 4; i++) {
        const int r = ty * 4 + i;
        const float inv = 1.0f / l_reg[i];
        float4 ov;
        upk2(ov.x, ov.y, o2[i][0]);
        upk2(ov.z, ov.w, o2[i][1]);
        ov.x *= inv; ov.y *= inv; ov.z *= inv; ov.w *= inv;
        *(float4*)(g_AO + (size_t)(b_ * SEQ + q0 + r) * DIM + h * HD + tx * 4) = ov;
    }
}

// ---------------------------------------------------------------------------
extern "C" void kernel_launch(void* const* d_in, const int* in_sizes, int n_in,
                              void* d_out, int out_size) {
    const float* x     = (const float*)d_in[0];
    const float* W_qkv = (const float*)d_in[1];
    const float* b_qkv = (const float*)d_in[2];
    const float* W_out = (const float*)d_in[3];
    const float* b_out = (const float*)d_in[4];
    float* out = (float*)d_out;

    const int n_x  = MTOT * DIM;     // 4194304
    const int n_wq = EQKV * DIM;     // 3145728
    const int n_wo = DIM * DIM;      // 1048576

    // 0) bf16 hi/lo splits of x and both weights
    cvt_split<0><<<n_x  / 1024, 256>>>(x,     n_x);
    cvt_split<1><<<n_wq / 1024, 256>>>(W_qkv, n_wq);
    cvt_split<2><<<n_wo / 1024, 256>>>(W_out, n_wo);

    // 1) QKV projection on tensor cores (cp.async pipeline, 2 CTAs/SM)
    const int gsmem = 2 * 4 * 128 * LDT * 2;   // 81920 B
    cudaFuncSetAttribute(gemm_mma<1>, cudaFuncAttributeMaxDynamicSharedMemorySize, gsmem);
    cudaFuncSetAttribute(gemm_mma<0>, cudaFuncAttributeMaxDynamicSharedMemorySize, gsmem);
    gemm_mma<1><<<dim3(EQKV / 128, MTOT / 128), 256, gsmem>>>(b_qkv, nullptr);

    // 2) Flash attention (fp32 f32x2, FMA-pipe exp)
    const int attn_smem = 4 * 64 * PAD * (int)sizeof(float);  // 69632
    cudaFuncSetAttribute(attn_fwd, cudaFuncAttributeMaxDynamicSharedMemorySize, attn_smem);
    attn_fwd<<<BATCH * HEADS * (SEQ / 64), 256, attn_smem>>>();

    // 3) AO -> bf16 hi/lo, then output projection on tensor cores
    cvt_split<3><<<n_x / 1024, 256>>>(nullptr, n_x);
    gemm_mma<0><<<dim3(DIM / 128, MTOT / 128), 256, gsmem>>>(b_out, out);
}

// round 17
// speedup vs baseline: 2.5478x; 1.7311x over previous
#include <cuda_runtime.h>
#include <cuda_bf16.h>
#include <math.h>
#include <stdint.h>

#define BATCH 2
#define SEQ   2048
#define DIM   1024
#define HEADS 16
#define HD    64
#define MTOT  (BATCH*SEQ)     // 4096
#define EQKV  (3*DIM)         // 3072
#define LDT   40              // gemm smem row stride (bf16)
#define LDQ   72              // attn smem row stride (bf16): 144B rows, conflict-free ldmatrix

typedef unsigned long long ull;

// ---------------------------------------------------------------------------
// Scratch (__device__ globals). HOUSE RULE: resolve in device code only.
// ---------------------------------------------------------------------------
__device__ __nv_bfloat16 g_xhi[(size_t)MTOT*DIM],  g_xlo[(size_t)MTOT*DIM];
__device__ __nv_bfloat16 g_wqh[(size_t)EQKV*DIM],  g_wql[(size_t)EQKV*DIM];
__device__ __nv_bfloat16 g_woh[(size_t)DIM*DIM],   g_wol[(size_t)DIM*DIM];
__device__ __nv_bfloat16 g_aoh[(size_t)MTOT*DIM],  g_aol[(size_t)MTOT*DIM];
// per-head Q/K/V, bf16 hi/lo, layout [b*H+h][n][hd]; Q pre-scaled by 0.125
__device__ __nv_bfloat16 g_qh[(size_t)BATCH*HEADS*SEQ*HD], g_ql[(size_t)BATCH*HEADS*SEQ*HD];
__device__ __nv_bfloat16 g_kh[(size_t)BATCH*HEADS*SEQ*HD], g_kl[(size_t)BATCH*HEADS*SEQ*HD];
__device__ __nv_bfloat16 g_vh[(size_t)BATCH*HEADS*SEQ*HD], g_vl[(size_t)BATCH*HEADS*SEQ*HD];

// ---- FMA-pipe exp (x <= 0, clamped; ~1e-7 rel) ----
__device__ __forceinline__ float fexpf(float x) {
    x = fmaxf(x, -87.0f);
    const float y = x * 1.4426950408889634f;
    const float r = rintf(y);
    const float f = y - r;
    float p =            1.5403530e-4f;
    p = fmaf(p, f, 1.3333558e-3f);
    p = fmaf(p, f, 9.6181291e-3f);
    p = fmaf(p, f, 5.5504109e-2f);
    p = fmaf(p, f, 2.4022651e-1f);
    p = fmaf(p, f, 6.9314718e-1f);
    p = fmaf(p, f, 1.0f);
    return __int_as_float(__float_as_int(p) + ((int)r << 23));
}

// ---- helpers (PTX target sm_103-safe, base ISA) ----
__device__ __forceinline__ uint32_t smem_u32(const void* p) {
    uint32_t a;
    asm("{ .reg .u64 t; cvta.to.shared.u64 t, %1; cvt.u32.u64 %0, t; }" : "=r"(a) : "l"(p));
    return a;
}
__device__ __forceinline__ void ldm_x4(uint32_t* r, uint32_t addr) {
    asm volatile("ldmatrix.sync.aligned.m8n8.x4.shared.b16 {%0,%1,%2,%3}, [%4];"
        : "=r"(r[0]), "=r"(r[1]), "=r"(r[2]), "=r"(r[3]) : "r"(addr));
}
__device__ __forceinline__ void ldm_x4t(uint32_t* r, uint32_t addr) {
    asm volatile("ldmatrix.sync.aligned.m8n8.x4.trans.shared.b16 {%0,%1,%2,%3}, [%4];"
        : "=r"(r[0]), "=r"(r[1]), "=r"(r[2]), "=r"(r[3]) : "r"(addr));
}
__device__ __forceinline__ void mma16816(float* c, const uint32_t* a, const uint32_t* b) {
    asm volatile("mma.sync.aligned.m16n8k16.row.col.f32.bf16.bf16.f32 "
        "{%0,%1,%2,%3}, {%4,%5,%6,%7}, {%8,%9}, {%0,%1,%2,%3};"
        : "+f"(c[0]), "+f"(c[1]), "+f"(c[2]), "+f"(c[3])
        : "r"(a[0]), "r"(a[1]), "r"(a[2]), "r"(a[3]), "r"(b[0]), "r"(b[1]));
}
#define CPA16(dst, src) \
    asm volatile("cp.async.cg.shared.global [%0], [%1], 16;" :: "r"(dst), "l"(src) : "memory")
#define CPA_COMMIT() asm volatile("cp.async.commit_group;" ::: "memory")
#define CPA_WAIT1()  asm volatile("cp.async.wait_group 1;" ::: "memory")
#define CPA_WAIT0()  asm volatile("cp.async.wait_group 0;" ::: "memory")

// split a float pair into packed bf16x2 hi and lo (lo = fp32 remainder)
__device__ __forceinline__ void split2(float x, float y, uint32_t& hi, uint32_t& lo) {
    __nv_bfloat16 hx = __float2bfloat16(x), hy = __float2bfloat16(y);
    __nv_bfloat162 h2 = __halves2bfloat162(hx, hy);
    hi = *(uint32_t*)&h2;
    __nv_bfloat162 l2 = __floats2bfloat162_rn(x - __bfloat162float(hx),
                                              y - __bfloat162float(hy));
    lo = *(uint32_t*)&l2;
}

// ---------------------------------------------------------------------------
// fp32 -> bf16 hi/lo split of inputs. W: 0 = x, 1 = W_qkv, 2 = W_out.
// ---------------------------------------------------------------------------
template<int W>
__global__ void __launch_bounds__(256) cvt_split(const float* __restrict__ src, int n) {
    __nv_bfloat16 *hi, *lo;
    if      (W == 0) { hi = g_xhi; lo = g_xlo; }
    else if (W == 1) { hi = g_wqh; lo = g_wql; }
    else             { hi = g_woh; lo = g_wol; }
    int i = (blockIdx.x * blockDim.x + threadIdx.x) * 4;
    if (i >= n) return;
    float4 v = *(const float4*)(src + i);
    uint32_t h0, l0, h1, l1;
    split2(v.x, v.y, h0, l0);
    split2(v.z, v.w, h1, l1);
    *(uint32_t*)(hi + i)     = h0;  *(uint32_t*)(hi + i + 2) = h1;
    *(uint32_t*)(lo + i)     = l0;  *(uint32_t*)(lo + i + 2) = l1;
}

// ---------------------------------------------------------------------------
// Tensor-core GEMM (round-16 proven core). QKV=1: epilogue splits to bf16
// hi/lo per-head Q/K/V (Q pre-scaled by 0.125). QKV=0: fp32 dense store.
// ---------------------------------------------------------------------------
template<int QKV>
__global__ void __launch_bounds__(256, 2) gemm_mma(const float* __restrict__ bias,
                                                  float* __restrict__ Cout) {
    extern __shared__ __align__(16) __nv_bfloat16 smb[];
    const int TILE = 128 * LDT;
    const uint32_t ub = smem_u32(smb);

    const int t = threadIdx.x;
    const int wid = t >> 5, lane = t & 31;
    const int wm = wid >> 1, wn = wid & 1;
    const int m0 = blockIdx.y * 128, e0 = blockIdx.x * 128;

    const __nv_bfloat16* Ahp = QKV ? g_xhi : g_aoh;
    const __nv_bfloat16* Alp = QKV ? g_xlo : g_aol;
    const __nv_bfloat16* Bhp = QKV ? g_wqh : g_woh;
    const __nv_bfloat16* Blp = QKV ? g_wql : g_wol;

    const int lrow = t >> 1;
    const int lu   = (t & 1) * 2;
    const __nv_bfloat16* gAh = Ahp + (size_t)(m0 + lrow) * DIM + lu * 8;
    const __nv_bfloat16* gAl = Alp + (size_t)(m0 + lrow) * DIM + lu * 8;
    const __nv_bfloat16* gBh = Bhp + (size_t)(e0 + lrow) * DIM + lu * 8;
    const __nv_bfloat16* gBl = Blp + (size_t)(e0 + lrow) * DIM + lu * 8;
    const uint32_t so = (uint32_t)(lrow * LDT + lu * 8) * 2;

#define PREF(k0, bufi) do { \
        const uint32_t d = ub + (uint32_t)(bufi) * 4u * TILE * 2u + so; \
        CPA16(d,            gAh + (k0)); CPA16(d + 16,            gAh + (k0) + 8); \
        CPA16(d + TILE*2,   gAl + (k0)); CPA16(d + TILE*2 + 16,   gAl + (k0) + 8); \
        CPA16(d + 2*TILE*2, gBh + (k0)); CPA16(d + 2*TILE*2 + 16, gBh + (k0) + 8); \
        CPA16(d + 3*TILE*2, gBl + (k0)); CPA16(d + 3*TILE*2 + 16, gBl + (k0) + 8); \
        CPA_COMMIT(); \
    } while (0)

    PREF(0, 0);

    float acc[2][8][4];
#pragma unroll
    for (int i = 0; i < 2; i++)
#pragma unroll
        for (int j = 0; j < 8; j++)
#pragma unroll
            for (int k = 0; k < 4; k++) acc[i][j][k] = 0.f;

    int buf = 0;
    for (int c = 0; c < 32; c++) {
        if (c < 31) { PREF((c + 1) * 32, buf ^ 1); CPA_WAIT1(); }
        else        { CPA_WAIT0(); }
        __syncthreads();

        const uint32_t sb = ub + (uint32_t)buf * 4 * TILE * 2;
#pragma unroll
        for (int ks = 0; ks < 2; ks++) {
            uint32_t fa[2][2][4];
#pragma unroll
            for (int mt = 0; mt < 2; mt++) {
                const int row = wm * 32 + mt * 16 + (lane & 15);
                const int col = ks * 16 + (lane >> 4) * 8;
                const uint32_t off = (uint32_t)(row * LDT + col) * 2;
                ldm_x4(fa[0][mt], sb + off);
                ldm_x4(fa[1][mt], sb + (uint32_t)TILE * 2 + off);
            }
            uint32_t fb[2][8][2];
#pragma unroll
            for (int pq = 0; pq < 4; pq++) {
                const int nr = wn * 64 + pq * 16 + ((lane >> 4) & 1) * 8 + (lane & 7);
                const int kc = ks * 16 + ((lane >> 3) & 1) * 8;
                const uint32_t off = (uint32_t)(nr * LDT + kc) * 2;
                uint32_t r[4];
                ldm_x4(r, sb + (uint32_t)(2 * TILE) * 2 + off);
                fb[0][2*pq][0] = r[0]; fb[0][2*pq][1] = r[1];
                fb[0][2*pq+1][0] = r[2]; fb[0][2*pq+1][1] = r[3];
                ldm_x4(r, sb + (uint32_t)(3 * TILE) * 2 + off);
                fb[1][2*pq][0] = r[0]; fb[1][2*pq][1] = r[1];
                fb[1][2*pq+1][0] = r[2]; fb[1][2*pq+1][1] = r[3];
            }
#pragma unroll
            for (int mt = 0; mt < 2; mt++)
#pragma unroll
                for (int nt = 0; nt < 8; nt++) {
                    mma16816(acc[mt][nt], fa[0][mt], fb[0][nt]);
                    mma16816(acc[mt][nt], fa[0][mt], fb[1][nt]);
                    mma16816(acc[mt][nt], fa[1][mt], fb[0][nt]);
                }
        }
        __syncthreads();
        buf ^= 1;
    }

#pragma unroll
    for (int mt = 0; mt < 2; mt++) {
        const int mbase = m0 + wm * 32 + mt * 16 + (lane >> 2);
#pragma unroll
        for (int nt = 0; nt < 8; nt++) {
            const int e = e0 + wn * 64 + nt * 8 + (lane & 3) * 2;
            const float bx = __ldg(bias + e), by = __ldg(bias + e + 1);
#pragma unroll
            for (int rh = 0; rh < 2; rh++) {
                const int m = mbase + rh * 8;
                float vx = acc[mt][nt][rh * 2 + 0] + bx;
                float vy = acc[mt][nt][rh * 2 + 1] + by;
                if (QKV) {
                    const int s  = e >> 10;             // 0=Q,1=K,2=V
                    const int h  = (e >> 6) & (HEADS - 1);
                    const int tc = e & (HD - 1);
                    if (s == 0) { vx *= 0.125f; vy *= 0.125f; }   // fold attn scale
                    __nv_bfloat16* dh = (s == 0) ? g_qh : ((s == 1) ? g_kh : g_vh);
                    __nv_bfloat16* dl = (s == 0) ? g_ql : ((s == 1) ? g_kl : g_vl);
                    const int b_ = m >> 11;
                    const int n  = m & (SEQ - 1);
                    const size_t idx = ((size_t)(b_ * HEADS + h) * SEQ + n) * HD + tc;
                    uint32_t hp, lp;
                    split2(vx, vy, hp, lp);
                    *(uint32_t*)(dh + idx) = hp;
                    *(uint32_t*)(dl + idx) = lp;
                } else {
                    *(float2*)(Cout + (size_t)m * DIM + e) = make_float2(vx, vy);
                }
            }
        }
    }
#undef PREF
}

// ---------------------------------------------------------------------------
// Flash attention on tensor cores (FA2 layout). Block = 128 queries, 8 warps
// (16 rows each, full 64-key j-tile per warp — no cross-warp softmax).
// S: 3-pass split-bf16 (K non-trans B). P kept in registers (C-frag == A-frag
// trick), split hi/lo, 3-pass PV with V via ldmatrix.x4.trans ([j][hd] tiles).
// Epilogue writes g_aoh/g_aol directly.
// ---------------------------------------------------------------------------
__global__ void __launch_bounds__(256) attn_mma() {
    extern __shared__ __align__(16) __nv_bfloat16 sma[];
    const uint32_t ub = smem_u32(sma);
    // smem layout (bf16 units)
    const int QH = 0,            QL = 128 * LDQ;          // 128x64 tiles
    const int KH = 2 * 128 * LDQ, KL = KH + 64 * LDQ;     // 64x64 tiles
    const int VH = KL + 64 * LDQ, VL = VH + 64 * LDQ;

    const int t = threadIdx.x;
    const int wid = t >> 5, lane = t & 31;
    const int blk = blockIdx.x;
    const int qt = blk & 15;           // SEQ/128 = 16 q-tiles
    const int bh = blk >> 4;
    const int q0 = qt * 128;
    const size_t base = (size_t)bh * SEQ * HD;

    // Load Q tiles (hi, lo): 128 rows x 64 cols, 8 bf16 per unit
    for (int u = t; u < 128 * 8; u += 256) {
        const int r = u >> 3, cu = (u & 7) * 8;
        const size_t g = base + (size_t)(q0 + r) * HD + cu;
        const int so = r * LDQ + cu;
        *(uint4*)(sma + QH + so) = *(const uint4*)(g_qh + g);
        *(uint4*)(sma + QL + so) = *(const uint4*)(g_ql + g);
    }

    float m0r = -1e30f, m1r = -1e30f, l0r = 0.f, l1r = 0.f;
    float o[8][4];
#pragma unroll
    for (int i = 0; i < 8; i++)
#pragma unroll
        for (int j = 0; j < 4; j++) o[i][j] = 0.f;

    const int m0w = wid * 16;

    for (int jt = 0; jt < 32; jt++) {
        const int j0 = jt * 64;
        __syncthreads();   // all warps done reading previous K/V
        for (int u = t; u < 64 * 8; u += 256) {
            const int r = u >> 3, cu = (u & 7) * 8;
            const size_t g = base + (size_t)(j0 + r) * HD + cu;
            const int so = r * LDQ + cu;
            *(uint4*)(sma + KH + so) = *(const uint4*)(g_kh + g);
            *(uint4*)(sma + KL + so) = *(const uint4*)(g_kl + g);
            *(uint4*)(sma + VH + so) = *(const uint4*)(g_vh + g);
            *(uint4*)(sma + VL + so) = *(const uint4*)(g_vl + g);
        }
        __syncthreads();

        // ---- S = Qs * K^T (3-pass split) ----
        float s[8][4];
#pragma unroll
        for (int i = 0; i < 8; i++)
#pragma unroll
            for (int j = 0; j < 4; j++) s[i][j] = 0.f;

#pragma unroll
        for (int ks = 0; ks < 4; ks++) {
            uint32_t ah[4], al[4];
            {
                const int row = m0w + (lane & 15);
                const int col = ks * 16 + (lane >> 4) * 8;
                const uint32_t off = (uint32_t)(row * LDQ + col) * 2;
                ldm_x4(ah, ub + QH * 2 + off);
                ldm_x4(al, ub + QL * 2 + off);
            }
#pragma unroll
            for (int pq = 0; pq < 4; pq++) {
                const int nr = pq * 16 + ((lane >> 4) & 1) * 8 + (lane & 7);
                const int kc = ks * 16 + ((lane >> 3) & 1) * 8;
                const uint32_t off = (uint32_t)(nr * LDQ + kc) * 2;
                uint32_t bhk[4], blk_[4];
                ldm_x4(bhk,  ub + KH * 2 + off);
                ldm_x4(blk_, ub + KL * 2 + off);
                uint32_t b0h[2] = {bhk[0], bhk[1]},  b1h[2] = {bhk[2], bhk[3]};
                uint32_t b0l[2] = {blk_[0], blk_[1]}, b1l[2] = {blk_[2], blk_[3]};
                mma16816(s[2*pq],   ah, b0h);
                mma16816(s[2*pq],   ah, b0l);
                mma16816(s[2*pq],   al, b0h);
                mma16816(s[2*pq+1], ah, b1h);
                mma16816(s[2*pq+1], ah, b1l);
                mma16816(s[2*pq+1], al, b1h);
            }
        }

        // ---- online softmax (rows r0 = m0w+(lane>>2), r1 = r0+8) ----
        float mx0 = -1e30f, mx1 = -1e30f;
#pragma unroll
        for (int nt = 0; nt < 8; nt++) {
            mx0 = fmaxf(mx0, fmaxf(s[nt][0], s[nt][1]));
            mx1 = fmaxf(mx1, fmaxf(s[nt][2], s[nt][3]));
        }
        mx0 = fmaxf(mx0, __shfl_xor_sync(0xffffffffu, mx0, 1));
        mx0 = fmaxf(mx0, __shfl_xor_sync(0xffffffffu, mx0, 2));
        mx1 = fmaxf(mx1, __shfl_xor_sync(0xffffffffu, mx1, 1));
        mx1 = fmaxf(mx1, __shfl_xor_sync(0xffffffffu, mx1, 2));
        const float mn0 = fmaxf(m0r, mx0), mn1 = fmaxf(m1r, mx1);
        float ss0 = 0.f, ss1 = 0.f;
#pragma unroll
        for (int nt = 0; nt < 8; nt++) {
            s[nt][0] = fexpf(s[nt][0] - mn0);
            s[nt][1] = fexpf(s[nt][1] - mn0);
            s[nt][2] = fexpf(s[nt][2] - mn1);
            s[nt][3] = fexpf(s[nt][3] - mn1);
            ss0 += s[nt][0] + s[nt][1];
            ss1 += s[nt][2] + s[nt][3];
        }
        ss0 += __shfl_xor_sync(0xffffffffu, ss0, 1);
        ss0 += __shfl_xor_sync(0xffffffffu, ss0, 2);
        ss1 += __shfl_xor_sync(0xffffffffu, ss1, 1);
        ss1 += __shfl_xor_sync(0xffffffffu, ss1, 2);
        const float a0 = fexpf(m0r - mn0), a1 = fexpf(m1r - mn1);
        l0r = l0r * a0 + ss0;  m0r = mn0;
        l1r = l1r * a1 + ss1;  m1r = mn1;
#pragma unroll
        for (int nt = 0; nt < 8; nt++) {
            o[nt][0] *= a0; o[nt][1] *= a0;
            o[nt][2] *= a1; o[nt][3] *= a1;
        }

        // ---- O += P * V (P from C-frags; 3-pass; V via ldmatrix.trans) ----
#pragma unroll
        for (int ks = 0; ks < 4; ks++) {
            uint32_t ah[4], al[4];
            split2(s[2*ks][0],   s[2*ks][1],   ah[0], al[0]);
            split2(s[2*ks][2],   s[2*ks][3],   ah[1], al[1]);
            split2(s[2*ks+1][0], s[2*ks+1][1], ah[2], al[2]);
            split2(s[2*ks+1][2], s[2*ks+1][3], ah[3], al[3]);
#pragma unroll
            for (int pq = 0; pq < 4; pq++) {
                const int kr = ks * 16 + ((lane >> 3) & 1) * 8 + (lane & 7);
                const int nc = pq * 16 + ((lane >> 4) & 1) * 8;
                const uint32_t off = (uint32_t)(kr * LDQ + nc) * 2;
                uint32_t bhv[4], blv[4];
                ldm_x4t(bhv, ub + VH * 2 + off);
                ldm_x4t(blv, ub + VL * 2 + off);
                uint32_t b0h[2] = {bhv[0], bhv[1]},  b1h[2] = {bhv[2], bhv[3]};
                uint32_t b0l[2] = {blv[0], blv[1]},  b1l[2] = {blv[2], blv[3]};
                mma16816(o[2*pq],   ah, b0h);
                mma16816(o[2*pq],   ah, b0l);
                mma16816(o[2*pq],   al, b0h);
                mma16816(o[2*pq+1], ah, b1h);
                mma16816(o[2*pq+1], ah, b1l);
                mma16816(o[2*pq+1], al, b1h);
            }
        }
    }

    // ---- finalize: /l, split hi/lo, write [B,N,D] ----
    const int b_ = bh >> 4;
    const int h  = bh & (HEADS - 1);
    const float inv0 = 1.0f / l0r, inv1 = 1.0f / l1r;
    const int row0 = b_ * SEQ + q0 + m0w + (lane >> 2);
#pragma unroll
    for (int nt = 0; nt < 8; nt++) {
        const int col = h * HD + nt * 8 + (lane & 3) * 2;
        uint32_t hp, lp;
        split2(o[nt][0] * inv0, o[nt][1] * inv0, hp, lp);
        *(uint32_t*)(g_aoh + (size_t)row0 * DIM + col) = hp;
        *(uint32_t*)(g_aol + (size_t)row0 * DIM + col) = lp;
        split2(o[nt][2] * inv1, o[nt][3] * inv1, hp, lp);
        *(uint32_t*)(g_aoh + (size_t)(row0 + 8) * DIM + col) = hp;
        *(uint32_t*)(g_aol + (size_t)(row0 + 8) * DIM + col) = lp;
    }
}

// ---------------------------------------------------------------------------
extern "C" void kernel_launch(void* const* d_in, const int* in_sizes, int n_in,
                              void* d_out, int out_size) {
    const float* x     = (const float*)d_in[0];
    const float* W_qkv = (const float*)d_in[1];
    const float* b_qkv = (const float*)d_in[2];
    const float* W_out = (const float*)d_in[3];
    const float* b_out = (const float*)d_in[4];
    float* out = (float*)d_out;

    const int n_x  = MTOT * DIM;
    const int n_wq = EQKV * DIM;
    const int n_wo = DIM * DIM;

    // 0) bf16 hi/lo splits of x and both weights
    cvt_split<0><<<n_x  / 1024, 256>>>(x,     n_x);
    cvt_split<1><<<n_wq / 1024, 256>>>(W_qkv, n_wq);
    cvt_split<2><<<n_wo / 1024, 256>>>(W_out, n_wo);

    // 1) QKV projection (tensor cores) -> per-head bf16 hi/lo Q/K/V
    const int gsmem = 2 * 4 * 128 * LDT * 2;   // 81920 B
    cudaFuncSetAttribute(gemm_mma<1>, cudaFuncAttributeMaxDynamicSharedMemorySize, gsmem);
    cudaFuncSetAttribute(gemm_mma<0>, cudaFuncAttributeMaxDynamicSharedMemorySize, gsmem);
    gemm_mma<1><<<dim3(EQKV / 128, MTOT / 128), 256, gsmem>>>(b_qkv, nullptr);

    // 2) Flash attention on tensor cores -> g_aoh/g_aol
    const int asmem = (2 * 128 * LDQ + 4 * 64 * LDQ) * 2;   // 73728 B
    cudaFuncSetAttribute(attn_mma, cudaFuncAttributeMaxDynamicSharedMemorySize, asmem);
    attn_mma<<<BATCH * HEADS * (SEQ / 128), 256, asmem>>>();

    // 3) Output projection (tensor cores) from g_aoh/g_aol
    gemm_mma<0><<<dim3(DIM / 128, MTOT / 128), 256, gsmem>>>(b_out, out);
}